// round 16
// baseline (speedup 1.0000x reference)
#include <cuda_runtime.h>
#include <cuda_bf16.h>
#include <math.h>
#include <stdint.h>

#define Bsz 32
#define Tlen 128
#define Hdim 1024
#define Vsz 32000
#define NB 128
#define NBG 64
#define NT 512
#define HB (Bsz * Hdim)

// ---------------- recurrence smem layout (byte offsets) ----------------
#define XSTR  1032                 // bf16 elems per full-K row (1024 + 8): bank-safe
#define XSTRB 2064
#define GTS2  136                  // gate W chunk stride (bf16 elems)
#define GTS2B 272
// mog: W full-K 16 rows at 0; X full-K 32 rows at 66048
#define MOG_WH 0
#define MOG_WL 33024
// gate: W 2 bufs of 34816 at 0
#define GW_H(b) ((b) * 34816)
#define GW_L(b) ((b) * 34816 + 17408)
// X region (shared by both stage types)
#define SXH 69632
#define SXL (69632 + 66048)
#define SP_OFF 0                   // P (32 KB) overlays W region, sync-separated
#define R_SMEM_BYTES (69632 + 2 * 66048)   // 201728

// ---------------- device scratch: activations as bf16 hi/lo pairs ----------------
__device__ __nv_bfloat16 g_XTh[(size_t)Tlen * HB], g_XTl[(size_t)Tlen * HB];
__device__ __nv_bfloat16 g_h1a_h[HB], g_h1a_l[HB], g_h1b_h[HB], g_h1b_l[HB];
__device__ __nv_bfloat16 g_h2a_h[HB], g_h2a_l[HB], g_h2b_h[HB], g_h2b_l[HB];
__device__ __nv_bfloat16 g_xA1_h[HB], g_xA1_l[HB], g_xB1_h[HB], g_xB1_l[HB];
__device__ __nv_bfloat16 g_hA1_h[HB], g_hA1_l[HB], g_hB1_h[HB], g_hB1_l[HB];
__device__ __nv_bfloat16 g_xA2_h[HB], g_xA2_l[HB], g_xB2_h[HB], g_xB2_l[HB];
__device__ __nv_bfloat16 g_hA2_h[HB], g_hA2_l[HB], g_hB2_h[HB], g_hB2_l[HB];
__device__ float g_c1[HB], g_c2[HB];
__device__ unsigned g_gcount;
__device__ volatile unsigned g_gsense;
__device__ unsigned g_lcount[2];
__device__ volatile unsigned g_lsense[2];

// bf16 hi/lo weight arena
#define WOFF_M1   0
#define WOFF_M2   5242880
#define WOFF_G1IH 10485760
#define WOFF_G1HH 14680064
#define WOFF_G2IH 18874368
#define WOFF_G2HH 23068672
#define WTOTAL    27262976
__device__ __nv_bfloat16 g_wh[WTOTAL];
__device__ __nv_bfloat16 g_wl[WTOTAL];

// bf16 hi/lo splits for logits GEMM (hid written directly by the recurrence)
__device__ __nv_bfloat16 g_embh[(size_t)Vsz * Hdim];
__device__ __nv_bfloat16 g_embl[(size_t)Vsz * Hdim];
__device__ __nv_bfloat16 g_hidh[(size_t)Bsz * Tlen * Hdim];
__device__ __nv_bfloat16 g_hidl[(size_t)Bsz * Tlen * Hdim];

// ---------------- barriers (sense reversing, replay-safe) ----------------
__device__ __forceinline__ void global_barrier(unsigned& sense) {
    __threadfence();
    __syncthreads();
    if (threadIdx.x == 0) {
        unsigned s = sense ^ 1u;
        if (atomicAdd(&g_gcount, 1u) == NB - 1u) {
            g_gcount = 0u;
            __threadfence();
            g_gsense = s;
        } else {
            while (g_gsense != s) __nanosleep(32);
        }
    }
    __syncthreads();
    __threadfence();
    sense ^= 1u;
}
__device__ __forceinline__ void group_barrier(int grp, unsigned& sense) {
    __threadfence();
    __syncthreads();
    if (threadIdx.x == 0) {
        unsigned s = sense ^ 1u;
        if (atomicAdd(&g_lcount[grp], 1u) == NBG - 1u) {
            g_lcount[grp] = 0u;
            __threadfence();
            g_lsense[grp] = s;
        } else {
            while (g_lsense[grp] != s) __nanosleep(32);
        }
    }
    __syncthreads();
    __threadfence();
    sense ^= 1u;
}

// ---------------- helpers ----------------
__device__ __forceinline__ void mma_bf16(float d[4], const uint32_t a[4],
                                         const uint32_t b[2]) {
    asm volatile(
        "mma.sync.aligned.m16n8k16.row.col.f32.bf16.bf16.f32 "
        "{%0,%1,%2,%3},{%4,%5,%6,%7},{%8,%9},{%0,%1,%2,%3};"
        : "+f"(d[0]), "+f"(d[1]), "+f"(d[2]), "+f"(d[3])
        : "r"(a[0]), "r"(a[1]), "r"(a[2]), "r"(a[3]), "r"(b[0]), "r"(b[1]));
}
__device__ __forceinline__ void cp16(uint32_t saddr, const void* g) {
    asm volatile("cp.async.cg.shared.global [%0], [%1], 16;" :: "r"(saddr), "l"(g));
}
#define CP_COMMIT() asm volatile("cp.async.commit_group;" ::: "memory")
template <int N>
__device__ __forceinline__ void cp_wait() {
    asm volatile("cp.async.wait_group %0;" :: "n"(N) : "memory");
}

// stage full-K X pair (32 rows x 1024) into SXH/SXL via cp.async (no commit)
__device__ __forceinline__ void stage_X(const __nv_bfloat16* __restrict__ Xh,
                                        const __nv_bfloat16* __restrict__ Xl,
                                        uint32_t smb) {
    int tid = threadIdx.x;
#pragma unroll
    for (int i = 0; i < 8; i++) {
        int idx = tid + i * NT;          // 0..4095
        int r = idx >> 7, u = idx & 127;
        size_t go = (size_t)r * Hdim + u * 8;
        uint32_t so = r * XSTRB + u * 16;
        cp16(smb + SXH + so, Xh + go);
        cp16(smb + SXL + so, Xl + go);
    }
}

// ---------------- mogrify stage: 16 rows/block, single-shot staging ----------------
// dst = mult * 2*sigmoid(W @ src + bias); all activations are bf16 hi/lo pairs
__device__ void mog_stage(const __nv_bfloat16* __restrict__ Wh,
                          const __nv_bfloat16* __restrict__ Wl,
                          const float* __restrict__ bias,
                          const __nv_bfloat16* __restrict__ srch,
                          const __nv_bfloat16* __restrict__ srcl,
                          const __nv_bfloat16* __restrict__ multh,
                          const __nv_bfloat16* __restrict__ multl,
                          __nv_bfloat16* __restrict__ dsth,
                          __nv_bfloat16* __restrict__ dstl,
                          int lb, char* sm, uint32_t smb)
{
    int tid = threadIdx.x, lane = tid & 31, w = tid >> 5;
    int gr = lane >> 2, tig = lane & 3;
    int j0 = lb * 16;
    float* P = (float*)(sm + SP_OFF);

    // stage W (16 rows x full K, hi+lo) + X, one cp.async group
#pragma unroll
    for (int i = 0; i < 4; i++) {
        int idx = tid + i * NT;          // 0..2047
        int r = idx >> 7, u = idx & 127;
        size_t go = (size_t)(j0 + r) * Hdim + u * 8;
        uint32_t so = r * XSTRB + u * 16;
        cp16(smb + MOG_WH + so, Wh + go);
        cp16(smb + MOG_WL + so, Wl + go);
    }
    stage_X(srch, srcl, smb);
    CP_COMMIT();
    cp_wait<0>();
    __syncthreads();

    const __nv_bfloat16* WhS = (const __nv_bfloat16*)(sm + MOG_WH);
    const __nv_bfloat16* WlS = (const __nv_bfloat16*)(sm + MOG_WL);
    const __nv_bfloat16* XhS = (const __nv_bfloat16*)(sm + SXH);
    const __nv_bfloat16* XlS = (const __nv_bfloat16*)(sm + SXL);

    float acc[4][4];
#pragma unroll
    for (int nf = 0; nf < 4; nf++)
#pragma unroll
        for (int q = 0; q < 4; q++) acc[nf][q] = 0.f;

#pragma unroll
    for (int c = 0; c < 4; c++) {
        int k0 = c * 256 + w * 16 + 2 * tig;
        uint32_t ah[4], al[4], bh[4][2], bl[4][2];
        int base = gr * XSTR + k0;
        ah[0] = *(const uint32_t*)&WhS[base];
        ah[1] = *(const uint32_t*)&WhS[base + 8 * XSTR];
        ah[2] = *(const uint32_t*)&WhS[base + 8];
        ah[3] = *(const uint32_t*)&WhS[base + 8 * XSTR + 8];
        al[0] = *(const uint32_t*)&WlS[base];
        al[1] = *(const uint32_t*)&WlS[base + 8 * XSTR];
        al[2] = *(const uint32_t*)&WlS[base + 8];
        al[3] = *(const uint32_t*)&WlS[base + 8 * XSTR + 8];
#pragma unroll
        for (int nf = 0; nf < 4; nf++) {
            int xb = (nf * 8 + gr) * XSTR + k0;
            bh[nf][0] = *(const uint32_t*)&XhS[xb];
            bh[nf][1] = *(const uint32_t*)&XhS[xb + 8];
            bl[nf][0] = *(const uint32_t*)&XlS[xb];
            bl[nf][1] = *(const uint32_t*)&XlS[xb + 8];
        }
#pragma unroll
        for (int nf = 0; nf < 4; nf++) {
            mma_bf16(acc[nf], ah, bh[nf]);
            mma_bf16(acc[nf], al, bh[nf]);
            mma_bf16(acc[nf], ah, bl[nf]);
        }
    }
    __syncthreads();   // W reads done before P overlays W region

#pragma unroll
    for (int nf = 0; nf < 4; nf++) {
        int cc = nf * 8 + 2 * tig;
        *(float2*)&P[w * 512 + gr * 32 + cc]       = make_float2(acc[nf][0], acc[nf][1]);
        *(float2*)&P[w * 512 + (gr + 8) * 32 + cc] = make_float2(acc[nf][2], acc[nf][3]);
    }
    __syncthreads();

    {
        float s = 0.f;
#pragma unroll
        for (int ww = 0; ww < 16; ww++) s += P[ww * 512 + tid];
        int row = tid >> 5, b = tid & 31;
        int j = j0 + row;
        s += bias[j];
        size_t o = (size_t)b * Hdim + j;
        float m = __bfloat162float(multh[o]) + __bfloat162float(multl[o]);
        float r = m * (2.f / (1.f + __expf(-s)));
        __nv_bfloat16 rh = __float2bfloat16_rn(r);
        dsth[o] = rh;
        dstl[o] = __float2bfloat16_rn(r - __bfloat162float(rh));
    }
}

// ---------------- gate stage: 64 rows/block, X staged once per source ----------------
__device__ void gate_stage(const __nv_bfloat16* __restrict__ WihH,
                           const __nv_bfloat16* __restrict__ WihL,
                           const __nv_bfloat16* __restrict__ WhhH,
                           const __nv_bfloat16* __restrict__ WhhL,
                           const float* __restrict__ bih, const float* __restrict__ bhh,
                           const __nv_bfloat16* __restrict__ xh,
                           const __nv_bfloat16* __restrict__ xl,
                           const __nv_bfloat16* __restrict__ hh,
                           const __nv_bfloat16* __restrict__ hl,
                           float* __restrict__ cSt,
                           __nv_bfloat16* __restrict__ hdh,
                           __nv_bfloat16* __restrict__ hdl,
                           float* __restrict__ hidOut,
                           __nv_bfloat16* __restrict__ gemmh,
                           __nv_bfloat16* __restrict__ gemml, int t,
                           int lb, char* sm, uint32_t smb)
{
    int tid = threadIdx.x, lane = tid & 31, w = tid >> 5;
    int gr = lane >> 2, tig = lane & 3;
    int mg = w >> 2, kg = w & 3;
    int j0u = lb * 16;
    float* P = (float*)(sm + SP_OFF);

    float acc[4][4];
#pragma unroll
    for (int nf = 0; nf < 4; nf++)
#pragma unroll
        for (int q = 0; q < 4; q++) acc[nf][q] = 0.f;

    auto stageW = [&](int buf, int cn) {
        const __nv_bfloat16* WmH = (cn < 8) ? WihH : WhhH;
        const __nv_bfloat16* WmL = (cn < 8) ? WihL : WhhL;
        int cbase = (cn & 7) * 128;
#pragma unroll
        for (int i = 0; i < 2; i++) {
            int idx = tid + i * NT;          // 0..1023
            int r = idx >> 4, u = idx & 15;  // row 0..63, unit 0..15
            int grow = (r >> 4) * Hdim + j0u + (r & 15);
            size_t go = (size_t)grow * Hdim + cbase + u * 8;
            cp16(smb + GW_H(buf) + r * GTS2B + u * 16, WmH + go);
            cp16(smb + GW_L(buf) + r * GTS2B + u * 16, WmL + go);
        }
        CP_COMMIT();
    };

    stage_X(xh, xl, smb);
    CP_COMMIT();
    stageW(0, 0);
    stageW(1, 1);

    const __nv_bfloat16* XhS = (const __nv_bfloat16*)(sm + SXH);
    const __nv_bfloat16* XlS = (const __nv_bfloat16*)(sm + SXL);

#pragma unroll
    for (int c = 0; c < 16; c++) {
        if (c == 15) cp_wait<0>(); else cp_wait<1>();
        __syncthreads();
        {
            const __nv_bfloat16* WhS = (const __nv_bfloat16*)(sm + GW_H(c & 1));
            const __nv_bfloat16* WlS = (const __nv_bfloat16*)(sm + GW_L(c & 1));
            int kX0 = (c & 7) * 128 + kg * 32;
            int kW0 = kg * 32;
#pragma unroll
            for (int ks = 0; ks < 2; ks++) {
                int kw = kW0 + ks * 16 + 2 * tig;
                int kx = kX0 + ks * 16 + 2 * tig;
                uint32_t ah[4], al[4], bh[4][2], bl[4][2];
                int base = (mg * 16 + gr) * GTS2 + kw;
                ah[0] = *(const uint32_t*)&WhS[base];
                ah[1] = *(const uint32_t*)&WhS[base + 8 * GTS2];
                ah[2] = *(const uint32_t*)&WhS[base + 8];
                ah[3] = *(const uint32_t*)&WhS[base + 8 * GTS2 + 8];
                al[0] = *(const uint32_t*)&WlS[base];
                al[1] = *(const uint32_t*)&WlS[base + 8 * GTS2];
                al[2] = *(const uint32_t*)&WlS[base + 8];
                al[3] = *(const uint32_t*)&WlS[base + 8 * GTS2 + 8];
#pragma unroll
                for (int nf = 0; nf < 4; nf++) {
                    int xb = (nf * 8 + gr) * XSTR + kx;
                    bh[nf][0] = *(const uint32_t*)&XhS[xb];
                    bh[nf][1] = *(const uint32_t*)&XhS[xb + 8];
                    bl[nf][0] = *(const uint32_t*)&XlS[xb];
                    bl[nf][1] = *(const uint32_t*)&XlS[xb + 8];
                }
#pragma unroll
                for (int nf = 0; nf < 4; nf++) {
                    mma_bf16(acc[nf], ah, bh[nf]);
                    mma_bf16(acc[nf], al, bh[nf]);
                    mma_bf16(acc[nf], ah, bl[nf]);
                }
            }
        }
        __syncthreads();
        if (c == 7) { stage_X(hh, hl, smb); CP_COMMIT(); }
        if (c + 2 < 16) stageW(c & 1, c + 2);
    }

    // P overlays W region (all W reads done; sync above)
#pragma unroll
    for (int nf = 0; nf < 4; nf++) {
        int cc = nf * 8 + 2 * tig;
        *(float2*)&P[kg * 2048 + (mg * 16 + gr) * 32 + cc] =
            make_float2(acc[nf][0], acc[nf][1]);
        *(float2*)&P[kg * 2048 + (mg * 16 + gr + 8) * 32 + cc] =
            make_float2(acc[nf][2], acc[nf][3]);
    }
    __syncthreads();

    {
        int u = tid >> 5, b = tid & 31;
        int j = j0u + u;
        float s[4];
#pragma unroll
        for (int g = 0; g < 4; g++) {
            int row = g * 16 + u;
            float v = 0.f;
#pragma unroll
            for (int k = 0; k < 4; k++) v += P[k * 2048 + row * 32 + b];
            s[g] = v;
        }
        float gi = s[0] + bih[j]            + bhh[j];
        float gf = s[1] + bih[Hdim + j]     + bhh[Hdim + j];
        float gg = s[2] + bih[2 * Hdim + j] + bhh[2 * Hdim + j];
        float go = s[3] + bih[3 * Hdim + j] + bhh[3 * Hdim + j];

        float si = 1.f / (1.f + __expf(-gi));
        float sf = 1.f / (1.f + __expf(-gf));
        float tg = tanhf(gg);
        float so = 1.f / (1.f + __expf(-go));

        size_t g = (size_t)b * Hdim + j;
        float cc = sf * cSt[g] + si * tg;
        float h = so * tanhf(cc);
        cSt[g] = cc;
        __nv_bfloat16 hh16 = __float2bfloat16_rn(h);
        __nv_bfloat16 hl16 = __float2bfloat16_rn(h - __bfloat162float(hh16));
        hdh[g] = hh16;
        hdl[g] = hl16;
        if (hidOut) {
            size_t oo = ((size_t)b * Tlen + t) * Hdim + j;
            hidOut[oo] = h;
            gemmh[oo] = hh16;
            gemml[oo] = hl16;
        }
    }
}

// ---------------- persistent recurrence kernel ----------------
__global__ __launch_bounds__(NT, 1) void mog_lstm_kernel(
    const int* __restrict__ seq,
    const float* __restrict__ m1b, const float* __restrict__ b1ih,
    const float* __restrict__ b1hh, const float* __restrict__ m2b,
    const float* __restrict__ b2ih, const float* __restrict__ b2hh,
    float* __restrict__ hidp)
{
    extern __shared__ char sm[];
    uint32_t smb;
    asm("{ .reg .u64 t; cvta.to.shared.u64 t, %1; cvt.u32.u64 %0, t; }"
        : "=r"(smb) : "l"(sm));
    int tid = threadIdx.x;
    int bid = blockIdx.x;
    int grp = bid >> 6;
    int lb  = bid & 63;
    unsigned gsn = 0, lsn = 0;

    // zero states (bf16 pairs + fp32 c)
    for (int g = bid * NT + tid; g < HB; g += NB * NT) {
        __nv_bfloat16 z = __float2bfloat16_rn(0.f);
        g_h1a_h[g] = z; g_h1a_l[g] = z; g_h1b_h[g] = z; g_h1b_l[g] = z;
        g_h2a_h[g] = z; g_h2a_l[g] = z; g_h2b_h[g] = z; g_h2b_l[g] = z;
        g_c1[g] = 0.f; g_c2[g] = 0.f;
    }
    // embedding gather: copy pre-split emb pairs into XT pairs
    {
        int t = bid;
        for (int idx = tid; idx < HB; idx += NT) {
            int b = idx >> 10, k = idx & 1023;
            int id = seq[b * Tlen + t];
            size_t d = ((size_t)t * Bsz + b) * Hdim + k;
            g_XTh[d] = g_embh[(size_t)id * Hdim + k];
            g_XTl[d] = g_embl[(size_t)id * Hdim + k];
        }
    }
    global_barrier(gsn);                                    // global #1

    const size_t MW = (size_t)Hdim * Hdim;
    for (int p = 0; p <= Tlen; p++) {
        bool Aact = (grp == 0) && (p < Tlen);
        bool Bact = (grp == 1) && (p >= 1);
        int t2 = p - 1;

        const __nv_bfloat16* A_xh = g_XTh + (size_t)p * HB;
        const __nv_bfloat16* A_xl = g_XTl + (size_t)p * HB;
        const __nv_bfloat16* A_hsh = (p & 1) ? g_h1b_h : g_h1a_h;
        const __nv_bfloat16* A_hsl = (p & 1) ? g_h1b_l : g_h1a_l;
        __nv_bfloat16* A_hdh = (p & 1) ? g_h1a_h : g_h1b_h;
        __nv_bfloat16* A_hdl = (p & 1) ? g_h1a_l : g_h1b_l;
        const __nv_bfloat16* B_xh = (t2 & 1) ? g_h1a_h : g_h1b_h;
        const __nv_bfloat16* B_xl = (t2 & 1) ? g_h1a_l : g_h1b_l;
        const __nv_bfloat16* B_hsh = (t2 & 1) ? g_h2b_h : g_h2a_h;
        const __nv_bfloat16* B_hsl = (t2 & 1) ? g_h2b_l : g_h2a_l;
        __nv_bfloat16* B_hdh = (t2 & 1) ? g_h2a_h : g_h2b_h;
        __nv_bfloat16* B_hdl = (t2 & 1) ? g_h2a_l : g_h2b_l;

        // mogrify rotation tables (src, mult, dst) as pairs
        const __nv_bfloat16* ASh[5] = { A_hsh, g_xA1_h, g_hA1_h, g_xB1_h, g_hB1_h };
        const __nv_bfloat16* ASl[5] = { A_hsl, g_xA1_l, g_hA1_l, g_xB1_l, g_hB1_l };
        const __nv_bfloat16* AMh[5] = { A_xh,  A_hsh,   g_xA1_h, g_hA1_h, g_xB1_h };
        const __nv_bfloat16* AMl[5] = { A_xl,  A_hsl,   g_xA1_l, g_hA1_l, g_xB1_l };
        __nv_bfloat16* ADh[5] = { g_xA1_h, g_hA1_h, g_xB1_h, g_hB1_h, g_xA1_h };
        __nv_bfloat16* ADl[5] = { g_xA1_l, g_hA1_l, g_xB1_l, g_hB1_l, g_xA1_l };

        const __nv_bfloat16* BSh[5] = { B_hsh, g_xA2_h, g_hA2_h, g_xB2_h, g_hB2_h };
        const __nv_bfloat16* BSl[5] = { B_hsl, g_xA2_l, g_hA2_l, g_xB2_l, g_hB2_l };
        const __nv_bfloat16* BMh[5] = { B_xh,  B_hsh,   g_xA2_h, g_hA2_h, g_xB2_h };
        const __nv_bfloat16* BMl[5] = { B_xl,  B_hsl,   g_xA2_l, g_hA2_l, g_xB2_l };
        __nv_bfloat16* BDh[5] = { g_xA2_h, g_hA2_h, g_xB2_h, g_hB2_h, g_xA2_h };
        __nv_bfloat16* BDl[5] = { g_xA2_l, g_hA2_l, g_xB2_l, g_hB2_l, g_xA2_l };

        for (int i = 0; i < 5; i++) {
            if (Aact)
                mog_stage(g_wh + WOFF_M1 + (size_t)i * MW, g_wl + WOFF_M1 + (size_t)i * MW,
                          m1b + i * Hdim, ASh[i], ASl[i], AMh[i], AMl[i],
                          ADh[i], ADl[i], lb, sm, smb);
            else if (Bact)
                mog_stage(g_wh + WOFF_M2 + (size_t)i * MW, g_wl + WOFF_M2 + (size_t)i * MW,
                          m2b + i * Hdim, BSh[i], BSl[i], BMh[i], BMl[i],
                          BDh[i], BDl[i], lb, sm, smb);
            group_barrier(grp, lsn);
        }
        if (Aact)
            gate_stage(g_wh + WOFF_G1IH, g_wl + WOFF_G1IH,
                       g_wh + WOFF_G1HH, g_wl + WOFF_G1HH,
                       b1ih, b1hh, g_xA1_h, g_xA1_l, g_hB1_h, g_hB1_l,
                       g_c1, A_hdh, A_hdl, nullptr, nullptr, nullptr, p,
                       lb, sm, smb);
        else if (Bact)
            gate_stage(g_wh + WOFF_G2IH, g_wl + WOFF_G2IH,
                       g_wh + WOFF_G2HH, g_wl + WOFF_G2HH,
                       b2ih, b2hh, g_xA2_h, g_xA2_l, g_hB2_h, g_hB2_l,
                       g_c2, B_hdh, B_hdl, hidp, g_hidh, g_hidl, t2,
                       lb, sm, smb);
        global_barrier(gsn);
    }
    group_barrier(grp, lsn);   // pad: group flips = 646 (even); global = 130 (even)
}

// ================= bf16 hi/lo split =================
__global__ void split_bf16_kernel(const float* __restrict__ src,
                                  __nv_bfloat16* __restrict__ hi,
                                  __nv_bfloat16* __restrict__ lo, size_t n4)
{
    for (size_t i = blockIdx.x * blockDim.x + threadIdx.x; i < n4;
         i += (size_t)gridDim.x * blockDim.x) {
        float4 v = *(const float4*)(src + i * 4);
        __nv_bfloat16 h0 = __float2bfloat16_rn(v.x);
        __nv_bfloat16 h1 = __float2bfloat16_rn(v.y);
        __nv_bfloat16 h2 = __float2bfloat16_rn(v.z);
        __nv_bfloat16 h3 = __float2bfloat16_rn(v.w);
        __nv_bfloat16 l0 = __float2bfloat16_rn(v.x - __bfloat162float(h0));
        __nv_bfloat16 l1 = __float2bfloat16_rn(v.y - __bfloat162float(h1));
        __nv_bfloat16 l2 = __float2bfloat16_rn(v.z - __bfloat162float(h2));
        __nv_bfloat16 l3 = __float2bfloat16_rn(v.w - __bfloat162float(h3));
        __nv_bfloat162* hp = (__nv_bfloat162*)(hi + i * 4);
        __nv_bfloat162* lp = (__nv_bfloat162*)(lo + i * 4);
        hp[0] = __nv_bfloat162(h0, h1);
        hp[1] = __nv_bfloat162(h2, h3);
        lp[0] = __nv_bfloat162(l0, l1);
        lp[1] = __nv_bfloat162(l2, l3);
    }
}

// ================= bf16x3 legacy-mma logits GEMM (unchanged, passing) =================
#define GTS 72
#define G_SMEM_BYTES (4 * 128 * GTS * 2)

__global__ __launch_bounds__(256, 2) void gemm_bf16x3_bias(
    const float* __restrict__ bias, float* __restrict__ C)
{
    extern __shared__ __nv_bfloat16 gs[];
    __nv_bfloat16* Ahs = gs;
    __nv_bfloat16* Als = Ahs + 128 * GTS;
    __nv_bfloat16* Bhs = Als + 128 * GTS;
    __nv_bfloat16* Bls = Bhs + 128 * GTS;

    int tid = threadIdx.x;
    int lane = tid & 31, wrp = tid >> 5;
    int wm = wrp & 1, wn = wrp >> 1;
    int gr = lane >> 2, tig = lane & 3;
    int m0 = blockIdx.x * 128;
    int n0 = blockIdx.y * 128;

    const __nv_bfloat16* Ahg = g_hidh + (size_t)m0 * Hdim;
    const __nv_bfloat16* Alg = g_hidl + (size_t)m0 * Hdim;
    const __nv_bfloat16* Bhg = g_embh + (size_t)n0 * Hdim;
    const __nv_bfloat16* Blg = g_embl + (size_t)n0 * Hdim;

    float acc[4][4][4];
#pragma unroll
    for (int i = 0; i < 4; i++)
#pragma unroll
        for (int j = 0; j < 4; j++)
#pragma unroll
            for (int q = 0; q < 4; q++) acc[i][j][q] = 0.f;

    for (int kc = 0; kc < Hdim; kc += 64) {
        __syncthreads();
#pragma unroll
        for (int i = 0; i < 4; i++) {
            int idx = tid + i * 256;
            int r = idx >> 3, u = idx & 7;
            int so = r * GTS + u * 8;
            size_t go = (size_t)r * Hdim + kc + u * 8;
            *(uint4*)&Ahs[so] = *(const uint4*)&Ahg[go];
            *(uint4*)&Als[so] = *(const uint4*)&Alg[go];
            *(uint4*)&Bhs[so] = *(const uint4*)&Bhg[go];
            *(uint4*)&Bls[so] = *(const uint4*)&Blg[go];
        }
        __syncthreads();

#pragma unroll
        for (int ks = 0; ks < 4; ks++) {
            int kb = ks * 16;
            uint32_t ah[4][4], al[4][4], bh[4][2], bl[4][2];
#pragma unroll
            for (int mf = 0; mf < 4; mf++) {
                int base = (wm * 64 + mf * 16 + gr) * GTS + kb + 2 * tig;
                ah[mf][0] = *(const uint32_t*)&Ahs[base];
                ah[mf][1] = *(const uint32_t*)&Ahs[base + 8 * GTS];
                ah[mf][2] = *(const uint32_t*)&Ahs[base + 8];
                ah[mf][3] = *(const uint32_t*)&Ahs[base + 8 * GTS + 8];
                al[mf][0] = *(const uint32_t*)&Als[base];
                al[mf][1] = *(const uint32_t*)&Als[base + 8 * GTS];
                al[mf][2] = *(const uint32_t*)&Als[base + 8];
                al[mf][3] = *(const uint32_t*)&Als[base + 8 * GTS + 8];
            }
#pragma unroll
            for (int nf = 0; nf < 4; nf++) {
                int base = (wn * 32 + nf * 8 + gr) * GTS + kb + 2 * tig;
                bh[nf][0] = *(const uint32_t*)&Bhs[base];
                bh[nf][1] = *(const uint32_t*)&Bhs[base + 8];
                bl[nf][0] = *(const uint32_t*)&Bls[base];
                bl[nf][1] = *(const uint32_t*)&Bls[base + 8];
            }
#pragma unroll
            for (int mf = 0; mf < 4; mf++)
#pragma unroll
                for (int nf = 0; nf < 4; nf++) {
                    mma_bf16(acc[mf][nf], ah[mf], bh[nf]);
                    mma_bf16(acc[mf][nf], al[mf], bh[nf]);
                    mma_bf16(acc[mf][nf], ah[mf], bl[nf]);
                }
        }
    }

#pragma unroll
    for (int nf = 0; nf < 4; nf++) {
        int col = n0 + wn * 32 + nf * 8 + 2 * tig;
        float bv0 = bias[col], bv1 = bias[col + 1];
#pragma unroll
        for (int mf = 0; mf < 4; mf++) {
            int row = m0 + wm * 64 + mf * 16 + gr;
            float2 v0 = make_float2(acc[mf][nf][0] + bv0, acc[mf][nf][1] + bv1);
            float2 v1 = make_float2(acc[mf][nf][2] + bv0, acc[mf][nf][3] + bv1);
            *(float2*)&C[(size_t)row * Vsz + col] = v0;
            *(float2*)&C[(size_t)(row + 8) * Vsz + col] = v1;
        }
    }
}

// ---------------- host ----------------
extern "C" void kernel_launch(void* const* d_in, const int* in_sizes, int n_in,
                              void* d_out, int out_size) {
    (void)in_sizes; (void)out_size;
    const int* seq = (const int*)d_in[0];
    int o = n_in - 14;
    const float* emb  = (const float*)d_in[o + 0];
    const float* fc_b = (const float*)d_in[o + 1];
    const float* m1w  = (const float*)d_in[o + 2];
    const float* m1b  = (const float*)d_in[o + 3];
    const float* w1ih = (const float*)d_in[o + 4];
    const float* w1hh = (const float*)d_in[o + 5];
    const float* b1ih = (const float*)d_in[o + 6];
    const float* b1hh = (const float*)d_in[o + 7];
    const float* m2w  = (const float*)d_in[o + 8];
    const float* m2b  = (const float*)d_in[o + 9];
    const float* w2ih = (const float*)d_in[o + 10];
    const float* w2hh = (const float*)d_in[o + 11];
    const float* b2ih = (const float*)d_in[o + 12];
    const float* b2hh = (const float*)d_in[o + 13];

    float* outp = (float*)d_out;                          // [B][T][V]
    float* hidp = outp + (size_t)Bsz * Tlen * Vsz;        // [B][T][H]

    __nv_bfloat16 *embh, *embl, *wh, *wl;
    cudaGetSymbolAddress((void**)&embh, g_embh);
    cudaGetSymbolAddress((void**)&embl, g_embl);
    cudaGetSymbolAddress((void**)&wh, g_wh);
    cudaGetSymbolAddress((void**)&wl, g_wl);

    cudaFuncSetAttribute(mog_lstm_kernel,
                         cudaFuncAttributeMaxDynamicSharedMemorySize, R_SMEM_BYTES);
    cudaFuncSetAttribute(gemm_bf16x3_bias,
                         cudaFuncAttributeMaxDynamicSharedMemorySize, G_SMEM_BYTES);

    // split weights into bf16 hi/lo arena
    split_bf16_kernel<<<512, 256>>>(m1w,  wh + WOFF_M1,   wl + WOFF_M1,   (size_t)5 * Hdim * Hdim / 4);
    split_bf16_kernel<<<512, 256>>>(m2w,  wh + WOFF_M2,   wl + WOFF_M2,   (size_t)5 * Hdim * Hdim / 4);
    split_bf16_kernel<<<512, 256>>>(w1ih, wh + WOFF_G1IH, wl + WOFF_G1IH, (size_t)4 * Hdim * Hdim / 4);
    split_bf16_kernel<<<512, 256>>>(w1hh, wh + WOFF_G1HH, wl + WOFF_G1HH, (size_t)4 * Hdim * Hdim / 4);
    split_bf16_kernel<<<512, 256>>>(w2ih, wh + WOFF_G2IH, wl + WOFF_G2IH, (size_t)4 * Hdim * Hdim / 4);
    split_bf16_kernel<<<512, 256>>>(w2hh, wh + WOFF_G2HH, wl + WOFF_G2HH, (size_t)4 * Hdim * Hdim / 4);

    // split embedding (recurrence gather + GEMM both read the pairs)
    split_bf16_kernel<<<2048, 256>>>(emb, embh, embl, (size_t)Vsz * Hdim / 4);

    mog_lstm_kernel<<<NB, NT, R_SMEM_BYTES>>>(seq, m1b, b1ih, b1hh,
                                              m2b, b2ih, b2hh, hidp);

    gemm_bf16x3_bias<<<dim3((Bsz * Tlen) / 128, Vsz / 128), 256, G_SMEM_BYTES>>>(fc_b, outp);
}

// round 17
// speedup vs baseline: 1.0672x; 1.0672x over previous
#include <cuda_runtime.h>
#include <cuda_bf16.h>
#include <math.h>
#include <stdint.h>

#define Bsz 32
#define Tlen 128
#define Hdim 1024
#define Vsz 32000
#define NB 128
#define NBG 64
#define NT 512
#define HB (Bsz * Hdim)

// ---------------- recurrence smem layout (byte offsets) ----------------
// mog chunk = 256 k: row stride 264 bf16 (528 B). gate chunk = 128 k: stride 136 (272 B)
#define MSTR 264
#define MSTRB 528
#define GSTR 136
#define GSTRB 272
// mog combined buffer: WH 8448 | WL 8448 | XH 16896 | XL 16896 = 50688
#define MBUF 50688
#define MW_H(b) ((b) * MBUF)
#define MW_L(b) ((b) * MBUF + 8448)
#define MX_H(b) ((b) * MBUF + 16896)
#define MX_L(b) ((b) * MBUF + 33792)
// gate combined buffer: WH 17408 | WL 17408 | XH 8704 | XL 8704 = 52224
#define GBUF 52224
#define GW_H(b) ((b) * GBUF)
#define GW_L(b) ((b) * GBUF + 17408)
#define GX_H(b) ((b) * GBUF + 34816)
#define GX_L(b) ((b) * GBUF + 43520)
#define SP_OFF 0                   // P (32 KB) overlays buffer 0, sync-separated
#define R_SMEM_BYTES (4 * GBUF)    // 208896

// ---------------- device scratch: activations as bf16 hi/lo pairs ----------------
__device__ __nv_bfloat16 g_XTh[(size_t)Tlen * HB], g_XTl[(size_t)Tlen * HB];
__device__ __nv_bfloat16 g_h1a_h[HB], g_h1a_l[HB], g_h1b_h[HB], g_h1b_l[HB];
__device__ __nv_bfloat16 g_h2a_h[HB], g_h2a_l[HB], g_h2b_h[HB], g_h2b_l[HB];
__device__ __nv_bfloat16 g_xA1_h[HB], g_xA1_l[HB], g_xB1_h[HB], g_xB1_l[HB];
__device__ __nv_bfloat16 g_hA1_h[HB], g_hA1_l[HB], g_hB1_h[HB], g_hB1_l[HB];
__device__ __nv_bfloat16 g_xA2_h[HB], g_xA2_l[HB], g_xB2_h[HB], g_xB2_l[HB];
__device__ __nv_bfloat16 g_hA2_h[HB], g_hA2_l[HB], g_hB2_h[HB], g_hB2_l[HB];
__device__ float g_c1[HB], g_c2[HB];
__device__ unsigned g_gcount;
__device__ volatile unsigned g_gsense;
__device__ unsigned g_lcount[2];
__device__ volatile unsigned g_lsense[2];

// bf16 hi/lo weight arena
#define WOFF_M1   0
#define WOFF_M2   5242880
#define WOFF_G1IH 10485760
#define WOFF_G1HH 14680064
#define WOFF_G2IH 18874368
#define WOFF_G2HH 23068672
#define WTOTAL    27262976
__device__ __nv_bfloat16 g_wh[WTOTAL];
__device__ __nv_bfloat16 g_wl[WTOTAL];

// bf16 hi/lo splits for logits GEMM (hid written directly by the recurrence)
__device__ __nv_bfloat16 g_embh[(size_t)Vsz * Hdim];
__device__ __nv_bfloat16 g_embl[(size_t)Vsz * Hdim];
__device__ __nv_bfloat16 g_hidh[(size_t)Bsz * Tlen * Hdim];
__device__ __nv_bfloat16 g_hidl[(size_t)Bsz * Tlen * Hdim];

// ---------------- barriers (sense reversing, replay-safe) ----------------
__device__ __forceinline__ void global_barrier(unsigned& sense) {
    __threadfence();
    __syncthreads();
    if (threadIdx.x == 0) {
        unsigned s = sense ^ 1u;
        if (atomicAdd(&g_gcount, 1u) == NB - 1u) {
            g_gcount = 0u;
            __threadfence();
            g_gsense = s;
        } else {
            while (g_gsense != s) __nanosleep(32);
        }
    }
    __syncthreads();
    __threadfence();
    sense ^= 1u;
}
__device__ __forceinline__ void group_barrier(int grp, unsigned& sense) {
    __threadfence();
    __syncthreads();
    if (threadIdx.x == 0) {
        unsigned s = sense ^ 1u;
        if (atomicAdd(&g_lcount[grp], 1u) == NBG - 1u) {
            g_lcount[grp] = 0u;
            __threadfence();
            g_lsense[grp] = s;
        } else {
            while (g_lsense[grp] != s) __nanosleep(32);
        }
    }
    __syncthreads();
    __threadfence();
    sense ^= 1u;
}

// ---------------- helpers ----------------
__device__ __forceinline__ void mma_bf16(float d[4], const uint32_t a[4],
                                         const uint32_t b[2]) {
    asm volatile(
        "mma.sync.aligned.m16n8k16.row.col.f32.bf16.bf16.f32 "
        "{%0,%1,%2,%3},{%4,%5,%6,%7},{%8,%9},{%0,%1,%2,%3};"
        : "+f"(d[0]), "+f"(d[1]), "+f"(d[2]), "+f"(d[3])
        : "r"(a[0]), "r"(a[1]), "r"(a[2]), "r"(a[3]), "r"(b[0]), "r"(b[1]));
}
__device__ __forceinline__ void cp16(uint32_t saddr, const void* g) {
    asm volatile("cp.async.cg.shared.global [%0], [%1], 16;" :: "r"(saddr), "l"(g));
}
#define CP_COMMIT() asm volatile("cp.async.commit_group;" ::: "memory")
template <int N>
__device__ __forceinline__ void cp_wait() {
    asm volatile("cp.async.wait_group %0;" :: "n"(N) : "memory");
}

// ---------------- mogrify stage: 16 rows/block, 4 pipelined combined chunks --------
// dst = mult * 2*sigmoid(W @ src + bias); all activations are bf16 hi/lo pairs
__device__ void mog_stage(const __nv_bfloat16* __restrict__ Wh,
                          const __nv_bfloat16* __restrict__ Wl,
                          const float* __restrict__ bias,
                          const __nv_bfloat16* __restrict__ srch,
                          const __nv_bfloat16* __restrict__ srcl,
                          const __nv_bfloat16* __restrict__ multh,
                          const __nv_bfloat16* __restrict__ multl,
                          __nv_bfloat16* __restrict__ dsth,
                          __nv_bfloat16* __restrict__ dstl,
                          int lb, char* sm, uint32_t smb)
{
    int tid = threadIdx.x, lane = tid & 31, w = tid >> 5;
    int gr = lane >> 2, tig = lane & 3;
    int j0 = lb * 16;
    float* P = (float*)(sm + SP_OFF);

    // issue all 4 chunk groups (W 16x256 + X 32x256, hi+lo each)
#pragma unroll
    for (int c = 0; c < 4; c++) {
        int cbase = c * 256;
        {   // W: 512 cp16 hi + 512 lo -> 1+1 per thread
            int r = tid >> 5, u = tid & 31;
            size_t go = (size_t)(j0 + r) * Hdim + cbase + u * 8;
            uint32_t so = r * MSTRB + u * 16;
            cp16(smb + MW_H(c) + so, Wh + go);
            cp16(smb + MW_L(c) + so, Wl + go);
        }
#pragma unroll
        for (int i = 0; i < 2; i++) {   // X: 1024 cp16 hi + 1024 lo -> 2+2 per thread
            int idx = tid + i * NT;
            int r = idx >> 5, u = idx & 31;
            size_t go = (size_t)r * Hdim + cbase + u * 8;
            uint32_t so = r * MSTRB + u * 16;
            cp16(smb + MX_H(c) + so, srch + go);
            cp16(smb + MX_L(c) + so, srcl + go);
        }
        CP_COMMIT();
    }

    float acc[4][4];
#pragma unroll
    for (int nf = 0; nf < 4; nf++)
#pragma unroll
        for (int q = 0; q < 4; q++) acc[nf][q] = 0.f;

#pragma unroll
    for (int c = 0; c < 4; c++) {
        if (c == 0) cp_wait<3>();
        else if (c == 1) cp_wait<2>();
        else if (c == 2) cp_wait<1>();
        else cp_wait<0>();
        __syncthreads();
        const __nv_bfloat16* WhS = (const __nv_bfloat16*)(sm + MW_H(c));
        const __nv_bfloat16* WlS = (const __nv_bfloat16*)(sm + MW_L(c));
        const __nv_bfloat16* XhS = (const __nv_bfloat16*)(sm + MX_H(c));
        const __nv_bfloat16* XlS = (const __nv_bfloat16*)(sm + MX_L(c));
        int k0 = w * 16 + 2 * tig;
        uint32_t ah[4], al[4], bh[4][2], bl[4][2];
        int base = gr * MSTR + k0;
        ah[0] = *(const uint32_t*)&WhS[base];
        ah[1] = *(const uint32_t*)&WhS[base + 8 * MSTR];
        ah[2] = *(const uint32_t*)&WhS[base + 8];
        ah[3] = *(const uint32_t*)&WhS[base + 8 * MSTR + 8];
        al[0] = *(const uint32_t*)&WlS[base];
        al[1] = *(const uint32_t*)&WlS[base + 8 * MSTR];
        al[2] = *(const uint32_t*)&WlS[base + 8];
        al[3] = *(const uint32_t*)&WlS[base + 8 * MSTR + 8];
#pragma unroll
        for (int nf = 0; nf < 4; nf++) {
            int xb = (nf * 8 + gr) * MSTR + k0;
            bh[nf][0] = *(const uint32_t*)&XhS[xb];
            bh[nf][1] = *(const uint32_t*)&XhS[xb + 8];
            bl[nf][0] = *(const uint32_t*)&XlS[xb];
            bl[nf][1] = *(const uint32_t*)&XlS[xb + 8];
        }
#pragma unroll
        for (int nf = 0; nf < 4; nf++) {
            mma_bf16(acc[nf], ah, bh[nf]);
            mma_bf16(acc[nf], al, bh[nf]);
            mma_bf16(acc[nf], ah, bl[nf]);
        }
    }
    __syncthreads();   // all frags done before P overlays buffer 0

#pragma unroll
    for (int nf = 0; nf < 4; nf++) {
        int cc = nf * 8 + 2 * tig;
        *(float2*)&P[w * 512 + gr * 32 + cc]       = make_float2(acc[nf][0], acc[nf][1]);
        *(float2*)&P[w * 512 + (gr + 8) * 32 + cc] = make_float2(acc[nf][2], acc[nf][3]);
    }
    __syncthreads();

    {
        float s = 0.f;
#pragma unroll
        for (int ww = 0; ww < 16; ww++) s += P[ww * 512 + tid];
        int row = tid >> 5, b = tid & 31;
        int j = j0 + row;
        s += bias[j];
        size_t o = (size_t)b * Hdim + j;
        float m = __bfloat162float(multh[o]) + __bfloat162float(multl[o]);
        float r = m * (2.f / (1.f + __expf(-s)));
        __nv_bfloat16 rh = __float2bfloat16_rn(r);
        dsth[o] = rh;
        dstl[o] = __float2bfloat16_rn(r - __bfloat162float(rh));
    }
}

// ---------------- gate stage: 64 rows/block, 16 chunks, 4 bufs, 3-ahead -------------
__device__ void gate_stage(const __nv_bfloat16* __restrict__ WihH,
                           const __nv_bfloat16* __restrict__ WihL,
                           const __nv_bfloat16* __restrict__ WhhH,
                           const __nv_bfloat16* __restrict__ WhhL,
                           const float* __restrict__ bih, const float* __restrict__ bhh,
                           const __nv_bfloat16* __restrict__ xh,
                           const __nv_bfloat16* __restrict__ xl,
                           const __nv_bfloat16* __restrict__ hh,
                           const __nv_bfloat16* __restrict__ hl,
                           float* __restrict__ cSt,
                           __nv_bfloat16* __restrict__ hdh,
                           __nv_bfloat16* __restrict__ hdl,
                           float* __restrict__ hidOut,
                           __nv_bfloat16* __restrict__ gemmh,
                           __nv_bfloat16* __restrict__ gemml, int t,
                           int lb, char* sm, uint32_t smb)
{
    int tid = threadIdx.x, lane = tid & 31, w = tid >> 5;
    int gr = lane >> 2, tig = lane & 3;
    int mg = w >> 2, kg = w & 3;
    int j0u = lb * 16;
    float* P = (float*)(sm + SP_OFF);

    float acc[4][4];
#pragma unroll
    for (int nf = 0; nf < 4; nf++)
#pragma unroll
        for (int q = 0; q < 4; q++) acc[nf][q] = 0.f;

    auto stageC = [&](int buf, int cn) {
        const __nv_bfloat16* WmH = (cn < 8) ? WihH : WhhH;
        const __nv_bfloat16* WmL = (cn < 8) ? WihL : WhhL;
        const __nv_bfloat16* XsH = (cn < 8) ? xh : hh;
        const __nv_bfloat16* XsL = (cn < 8) ? xl : hl;
        int cbase = (cn & 7) * 128;
#pragma unroll
        for (int i = 0; i < 2; i++) {       // W: 1024 cp16 hi + lo
            int idx = tid + i * NT;
            int r = idx >> 4, u = idx & 15;
            int grow = (r >> 4) * Hdim + j0u + (r & 15);
            size_t go = (size_t)grow * Hdim + cbase + u * 8;
            uint32_t so = r * GSTRB + u * 16;
            cp16(smb + GW_H(buf) + so, WmH + go);
            cp16(smb + GW_L(buf) + so, WmL + go);
        }
        {                                   // X: 512 cp16 hi + lo
            int r = tid >> 4, u = tid & 15;
            size_t go = (size_t)r * Hdim + cbase + u * 8;
            uint32_t so = r * GSTRB + u * 16;
            cp16(smb + GX_H(buf) + so, XsH + go);
            cp16(smb + GX_L(buf) + so, XsL + go);
        }
        CP_COMMIT();
    };

    stageC(0, 0);
    stageC(1, 1);
    stageC(2, 2);

#pragma unroll
    for (int c = 0; c < 16; c++) {
        if (c + 3 < 16) stageC((c + 3) & 3, c + 3);
        if (c <= 12) cp_wait<3>();
        else if (c == 13) cp_wait<2>();
        else if (c == 14) cp_wait<1>();
        else cp_wait<0>();
        __syncthreads();
        {
            const __nv_bfloat16* WhS = (const __nv_bfloat16*)(sm + GW_H(c & 3));
            const __nv_bfloat16* WlS = (const __nv_bfloat16*)(sm + GW_L(c & 3));
            const __nv_bfloat16* XhS = (const __nv_bfloat16*)(sm + GX_H(c & 3));
            const __nv_bfloat16* XlS = (const __nv_bfloat16*)(sm + GX_L(c & 3));
#pragma unroll
            for (int ks = 0; ks < 2; ks++) {
                int k0 = kg * 32 + ks * 16 + 2 * tig;
                uint32_t ah[4], al[4], bh[4][2], bl[4][2];
                int base = (mg * 16 + gr) * GSTR + k0;
                ah[0] = *(const uint32_t*)&WhS[base];
                ah[1] = *(const uint32_t*)&WhS[base + 8 * GSTR];
                ah[2] = *(const uint32_t*)&WhS[base + 8];
                ah[3] = *(const uint32_t*)&WhS[base + 8 * GSTR + 8];
                al[0] = *(const uint32_t*)&WlS[base];
                al[1] = *(const uint32_t*)&WlS[base + 8 * GSTR];
                al[2] = *(const uint32_t*)&WlS[base + 8];
                al[3] = *(const uint32_t*)&WlS[base + 8 * GSTR + 8];
#pragma unroll
                for (int nf = 0; nf < 4; nf++) {
                    int xb = (nf * 8 + gr) * GSTR + k0;
                    bh[nf][0] = *(const uint32_t*)&XhS[xb];
                    bh[nf][1] = *(const uint32_t*)&XhS[xb + 8];
                    bl[nf][0] = *(const uint32_t*)&XlS[xb];
                    bl[nf][1] = *(const uint32_t*)&XlS[xb + 8];
                }
#pragma unroll
                for (int nf = 0; nf < 4; nf++) {
                    mma_bf16(acc[nf], ah, bh[nf]);
                    mma_bf16(acc[nf], al, bh[nf]);
                    mma_bf16(acc[nf], ah, bl[nf]);
                }
            }
        }
        __syncthreads();   // buffer reuse safety (reused 4 chunks later)
    }

    // P overlays buffer 0 (frag reads of buf0 completed; trailing syncs)
#pragma unroll
    for (int nf = 0; nf < 4; nf++) {
        int cc = nf * 8 + 2 * tig;
        *(float2*)&P[kg * 2048 + (mg * 16 + gr) * 32 + cc] =
            make_float2(acc[nf][0], acc[nf][1]);
        *(float2*)&P[kg * 2048 + (mg * 16 + gr + 8) * 32 + cc] =
            make_float2(acc[nf][2], acc[nf][3]);
    }
    __syncthreads();

    {
        int u = tid >> 5, b = tid & 31;
        int j = j0u + u;
        float s[4];
#pragma unroll
        for (int g = 0; g < 4; g++) {
            int row = g * 16 + u;
            float v = 0.f;
#pragma unroll
            for (int k = 0; k < 4; k++) v += P[k * 2048 + row * 32 + b];
            s[g] = v;
        }
        float gi = s[0] + bih[j]            + bhh[j];
        float gf = s[1] + bih[Hdim + j]     + bhh[Hdim + j];
        float gg = s[2] + bih[2 * Hdim + j] + bhh[2 * Hdim + j];
        float go = s[3] + bih[3 * Hdim + j] + bhh[3 * Hdim + j];

        float si = 1.f / (1.f + __expf(-gi));
        float sf = 1.f / (1.f + __expf(-gf));
        float tg = tanhf(gg);
        float so = 1.f / (1.f + __expf(-go));

        size_t g = (size_t)b * Hdim + j;
        float cc = sf * cSt[g] + si * tg;
        float h = so * tanhf(cc);
        cSt[g] = cc;
        __nv_bfloat16 hh16 = __float2bfloat16_rn(h);
        __nv_bfloat16 hl16 = __float2bfloat16_rn(h - __bfloat162float(hh16));
        hdh[g] = hh16;
        hdl[g] = hl16;
        if (hidOut) {
            size_t oo = ((size_t)b * Tlen + t) * Hdim + j;
            hidOut[oo] = h;
            gemmh[oo] = hh16;
            gemml[oo] = hl16;
        }
    }
}

// ---------------- persistent recurrence kernel ----------------
__global__ __launch_bounds__(NT, 1) void mog_lstm_kernel(
    const int* __restrict__ seq,
    const float* __restrict__ m1b, const float* __restrict__ b1ih,
    const float* __restrict__ b1hh, const float* __restrict__ m2b,
    const float* __restrict__ b2ih, const float* __restrict__ b2hh,
    float* __restrict__ hidp)
{
    extern __shared__ char sm[];
    uint32_t smb;
    asm("{ .reg .u64 t; cvta.to.shared.u64 t, %1; cvt.u32.u64 %0, t; }"
        : "=r"(smb) : "l"(sm));
    int tid = threadIdx.x;
    int bid = blockIdx.x;
    int grp = bid >> 6;
    int lb  = bid & 63;
    unsigned gsn = 0, lsn = 0;

    for (int g = bid * NT + tid; g < HB; g += NB * NT) {
        __nv_bfloat16 z = __float2bfloat16_rn(0.f);
        g_h1a_h[g] = z; g_h1a_l[g] = z; g_h1b_h[g] = z; g_h1b_l[g] = z;
        g_h2a_h[g] = z; g_h2a_l[g] = z; g_h2b_h[g] = z; g_h2b_l[g] = z;
        g_c1[g] = 0.f; g_c2[g] = 0.f;
    }
    {
        int t = bid;
        for (int idx = tid; idx < HB; idx += NT) {
            int b = idx >> 10, k = idx & 1023;
            int id = seq[b * Tlen + t];
            size_t d = ((size_t)t * Bsz + b) * Hdim + k;
            g_XTh[d] = g_embh[(size_t)id * Hdim + k];
            g_XTl[d] = g_embl[(size_t)id * Hdim + k];
        }
    }
    global_barrier(gsn);                                    // global #1

    const size_t MW = (size_t)Hdim * Hdim;
    for (int p = 0; p <= Tlen; p++) {
        bool Aact = (grp == 0) && (p < Tlen);
        bool Bact = (grp == 1) && (p >= 1);
        int t2 = p - 1;

        const __nv_bfloat16* A_xh = g_XTh + (size_t)p * HB;
        const __nv_bfloat16* A_xl = g_XTl + (size_t)p * HB;
        const __nv_bfloat16* A_hsh = (p & 1) ? g_h1b_h : g_h1a_h;
        const __nv_bfloat16* A_hsl = (p & 1) ? g_h1b_l : g_h1a_l;
        __nv_bfloat16* A_hdh = (p & 1) ? g_h1a_h : g_h1b_h;
        __nv_bfloat16* A_hdl = (p & 1) ? g_h1a_l : g_h1b_l;
        const __nv_bfloat16* B_xh = (t2 & 1) ? g_h1a_h : g_h1b_h;
        const __nv_bfloat16* B_xl = (t2 & 1) ? g_h1a_l : g_h1b_l;
        const __nv_bfloat16* B_hsh = (t2 & 1) ? g_h2b_h : g_h2a_h;
        const __nv_bfloat16* B_hsl = (t2 & 1) ? g_h2b_l : g_h2a_l;
        __nv_bfloat16* B_hdh = (t2 & 1) ? g_h2a_h : g_h2b_h;
        __nv_bfloat16* B_hdl = (t2 & 1) ? g_h2a_l : g_h2b_l;

        const __nv_bfloat16* ASh[5] = { A_hsh, g_xA1_h, g_hA1_h, g_xB1_h, g_hB1_h };
        const __nv_bfloat16* ASl[5] = { A_hsl, g_xA1_l, g_hA1_l, g_xB1_l, g_hB1_l };
        const __nv_bfloat16* AMh[5] = { A_xh,  A_hsh,   g_xA1_h, g_hA1_h, g_xB1_h };
        const __nv_bfloat16* AMl[5] = { A_xl,  A_hsl,   g_xA1_l, g_hA1_l, g_xB1_l };
        __nv_bfloat16* ADh[5] = { g_xA1_h, g_hA1_h, g_xB1_h, g_hB1_h, g_xA1_h };
        __nv_bfloat16* ADl[5] = { g_xA1_l, g_hA1_l, g_xB1_l, g_hB1_l, g_xA1_l };

        const __nv_bfloat16* BSh[5] = { B_hsh, g_xA2_h, g_hA2_h, g_xB2_h, g_hB2_h };
        const __nv_bfloat16* BSl[5] = { B_hsl, g_xA2_l, g_hA2_l, g_xB2_l, g_hB2_l };
        const __nv_bfloat16* BMh[5] = { B_xh,  B_hsh,   g_xA2_h, g_hA2_h, g_xB2_h };
        const __nv_bfloat16* BMl[5] = { B_xl,  B_hsl,   g_xA2_l, g_hA2_l, g_xB2_l };
        __nv_bfloat16* BDh[5] = { g_xA2_h, g_hA2_h, g_xB2_h, g_hB2_h, g_xA2_h };
        __nv_bfloat16* BDl[5] = { g_xA2_l, g_hA2_l, g_xB2_l, g_hB2_l, g_xA2_l };

        for (int i = 0; i < 5; i++) {
            if (Aact)
                mog_stage(g_wh + WOFF_M1 + (size_t)i * MW, g_wl + WOFF_M1 + (size_t)i * MW,
                          m1b + i * Hdim, ASh[i], ASl[i], AMh[i], AMl[i],
                          ADh[i], ADl[i], lb, sm, smb);
            else if (Bact)
                mog_stage(g_wh + WOFF_M2 + (size_t)i * MW, g_wl + WOFF_M2 + (size_t)i * MW,
                          m2b + i * Hdim, BSh[i], BSl[i], BMh[i], BMl[i],
                          BDh[i], BDl[i], lb, sm, smb);
            group_barrier(grp, lsn);
        }
        if (Aact)
            gate_stage(g_wh + WOFF_G1IH, g_wl + WOFF_G1IH,
                       g_wh + WOFF_G1HH, g_wl + WOFF_G1HH,
                       b1ih, b1hh, g_xA1_h, g_xA1_l, g_hB1_h, g_hB1_l,
                       g_c1, A_hdh, A_hdl, nullptr, nullptr, nullptr, p,
                       lb, sm, smb);
        else if (Bact)
            gate_stage(g_wh + WOFF_G2IH, g_wl + WOFF_G2IH,
                       g_wh + WOFF_G2HH, g_wl + WOFF_G2HH,
                       b2ih, b2hh, g_xA2_h, g_xA2_l, g_hB2_h, g_hB2_l,
                       g_c2, B_hdh, B_hdl, hidp, g_hidh, g_hidl, t2,
                       lb, sm, smb);
        global_barrier(gsn);
    }
    group_barrier(grp, lsn);   // pad: group flips = 646 (even); global = 130 (even)
}

// ================= bf16 hi/lo split =================
__global__ void split_bf16_kernel(const float* __restrict__ src,
                                  __nv_bfloat16* __restrict__ hi,
                                  __nv_bfloat16* __restrict__ lo, size_t n4)
{
    for (size_t i = blockIdx.x * blockDim.x + threadIdx.x; i < n4;
         i += (size_t)gridDim.x * blockDim.x) {
        float4 v = *(const float4*)(src + i * 4);
        __nv_bfloat16 h0 = __float2bfloat16_rn(v.x);
        __nv_bfloat16 h1 = __float2bfloat16_rn(v.y);
        __nv_bfloat16 h2 = __float2bfloat16_rn(v.z);
        __nv_bfloat16 h3 = __float2bfloat16_rn(v.w);
        __nv_bfloat16 l0 = __float2bfloat16_rn(v.x - __bfloat162float(h0));
        __nv_bfloat16 l1 = __float2bfloat16_rn(v.y - __bfloat162float(h1));
        __nv_bfloat16 l2 = __float2bfloat16_rn(v.z - __bfloat162float(h2));
        __nv_bfloat16 l3 = __float2bfloat16_rn(v.w - __bfloat162float(h3));
        __nv_bfloat162* hp = (__nv_bfloat162*)(hi + i * 4);
        __nv_bfloat162* lp = (__nv_bfloat162*)(lo + i * 4);
        hp[0] = __nv_bfloat162(h0, h1);
        hp[1] = __nv_bfloat162(h2, h3);
        lp[0] = __nv_bfloat162(l0, l1);
        lp[1] = __nv_bfloat162(l2, l3);
    }
}

// ================= bf16x3 legacy-mma logits GEMM (unchanged, passing) =================
#define GTS 72
#define G_SMEM_BYTES (4 * 128 * GTS * 2)

__global__ __launch_bounds__(256, 2) void gemm_bf16x3_bias(
    const float* __restrict__ bias, float* __restrict__ C)
{
    extern __shared__ __nv_bfloat16 gs[];
    __nv_bfloat16* Ahs = gs;
    __nv_bfloat16* Als = Ahs + 128 * GTS;
    __nv_bfloat16* Bhs = Als + 128 * GTS;
    __nv_bfloat16* Bls = Bhs + 128 * GTS;

    int tid = threadIdx.x;
    int lane = tid & 31, wrp = tid >> 5;
    int wm = wrp & 1, wn = wrp >> 1;
    int gr = lane >> 2, tig = lane & 3;
    int m0 = blockIdx.x * 128;
    int n0 = blockIdx.y * 128;

    const __nv_bfloat16* Ahg = g_hidh + (size_t)m0 * Hdim;
    const __nv_bfloat16* Alg = g_hidl + (size_t)m0 * Hdim;
    const __nv_bfloat16* Bhg = g_embh + (size_t)n0 * Hdim;
    const __nv_bfloat16* Blg = g_embl + (size_t)n0 * Hdim;

    float acc[4][4][4];
#pragma unroll
    for (int i = 0; i < 4; i++)
#pragma unroll
        for (int j = 0; j < 4; j++)
#pragma unroll
            for (int q = 0; q < 4; q++) acc[i][j][q] = 0.f;

    for (int kc = 0; kc < Hdim; kc += 64) {
        __syncthreads();
#pragma unroll
        for (int i = 0; i < 4; i++) {
            int idx = tid + i * 256;
            int r = idx >> 3, u = idx & 7;
            int so = r * GTS + u * 8;
            size_t go = (size_t)r * Hdim + kc + u * 8;
            *(uint4*)&Ahs[so] = *(const uint4*)&Ahg[go];
            *(uint4*)&Als[so] = *(const uint4*)&Alg[go];
            *(uint4*)&Bhs[so] = *(const uint4*)&Bhg[go];
            *(uint4*)&Bls[so] = *(const uint4*)&Blg[go];
        }
        __syncthreads();

#pragma unroll
        for (int ks = 0; ks < 4; ks++) {
            int kb = ks * 16;
            uint32_t ah[4][4], al[4][4], bh[4][2], bl[4][2];
#pragma unroll
            for (int mf = 0; mf < 4; mf++) {
                int base = (wm * 64 + mf * 16 + gr) * GTS + kb + 2 * tig;
                ah[mf][0] = *(const uint32_t*)&Ahs[base];
                ah[mf][1] = *(const uint32_t*)&Ahs[base + 8 * GTS];
                ah[mf][2] = *(const uint32_t*)&Ahs[base + 8];
                ah[mf][3] = *(const uint32_t*)&Ahs[base + 8 * GTS + 8];
                al[mf][0] = *(const uint32_t*)&Als[base];
                al[mf][1] = *(const uint32_t*)&Als[base + 8 * GTS];
                al[mf][2] = *(const uint32_t*)&Als[base + 8];
                al[mf][3] = *(const uint32_t*)&Als[base + 8 * GTS + 8];
            }
#pragma unroll
            for (int nf = 0; nf < 4; nf++) {
                int base = (wn * 32 + nf * 8 + gr) * GTS + kb + 2 * tig;
                bh[nf][0] = *(const uint32_t*)&Bhs[base];
                bh[nf][1] = *(const uint32_t*)&Bhs[base + 8];
                bl[nf][0] = *(const uint32_t*)&Bls[base];
                bl[nf][1] = *(const uint32_t*)&Bls[base + 8];
            }
#pragma unroll
            for (int mf = 0; mf < 4; mf++)
#pragma unroll
                for (int nf = 0; nf < 4; nf++) {
                    mma_bf16(acc[mf][nf], ah[mf], bh[nf]);
                    mma_bf16(acc[mf][nf], al[mf], bh[nf]);
                    mma_bf16(acc[mf][nf], ah[mf], bl[nf]);
                }
        }
    }

#pragma unroll
    for (int nf = 0; nf < 4; nf++) {
        int col = n0 + wn * 32 + nf * 8 + 2 * tig;
        float bv0 = bias[col], bv1 = bias[col + 1];
#pragma unroll
        for (int mf = 0; mf < 4; mf++) {
            int row = m0 + wm * 64 + mf * 16 + gr;
            float2 v0 = make_float2(acc[mf][nf][0] + bv0, acc[mf][nf][1] + bv1);
            float2 v1 = make_float2(acc[mf][nf][2] + bv0, acc[mf][nf][3] + bv1);
            *(float2*)&C[(size_t)row * Vsz + col] = v0;
            *(float2*)&C[(size_t)(row + 8) * Vsz + col] = v1;
        }
    }
}

// ---------------- host ----------------
extern "C" void kernel_launch(void* const* d_in, const int* in_sizes, int n_in,
                              void* d_out, int out_size) {
    (void)in_sizes; (void)out_size;
    const int* seq = (const int*)d_in[0];
    int o = n_in - 14;
    const float* emb  = (const float*)d_in[o + 0];
    const float* fc_b = (const float*)d_in[o + 1];
    const float* m1w  = (const float*)d_in[o + 2];
    const float* m1b  = (const float*)d_in[o + 3];
    const float* w1ih = (const float*)d_in[o + 4];
    const float* w1hh = (const float*)d_in[o + 5];
    const float* b1ih = (const float*)d_in[o + 6];
    const float* b1hh = (const float*)d_in[o + 7];
    const float* m2w  = (const float*)d_in[o + 8];
    const float* m2b  = (const float*)d_in[o + 9];
    const float* w2ih = (const float*)d_in[o + 10];
    const float* w2hh = (const float*)d_in[o + 11];
    const float* b2ih = (const float*)d_in[o + 12];
    const float* b2hh = (const float*)d_in[o + 13];

    float* outp = (float*)d_out;                          // [B][T][V]
    float* hidp = outp + (size_t)Bsz * Tlen * Vsz;        // [B][T][H]

    __nv_bfloat16 *embh, *embl, *wh, *wl;
    cudaGetSymbolAddress((void**)&embh, g_embh);
    cudaGetSymbolAddress((void**)&embl, g_embl);
    cudaGetSymbolAddress((void**)&wh, g_wh);
    cudaGetSymbolAddress((void**)&wl, g_wl);

    cudaFuncSetAttribute(mog_lstm_kernel,
                         cudaFuncAttributeMaxDynamicSharedMemorySize, R_SMEM_BYTES);
    cudaFuncSetAttribute(gemm_bf16x3_bias,
                         cudaFuncAttributeMaxDynamicSharedMemorySize, G_SMEM_BYTES);

    // split weights into bf16 hi/lo arena
    split_bf16_kernel<<<512, 256>>>(m1w,  wh + WOFF_M1,   wl + WOFF_M1,   (size_t)5 * Hdim * Hdim / 4);
    split_bf16_kernel<<<512, 256>>>(m2w,  wh + WOFF_M2,   wl + WOFF_M2,   (size_t)5 * Hdim * Hdim / 4);
    split_bf16_kernel<<<512, 256>>>(w1ih, wh + WOFF_G1IH, wl + WOFF_G1IH, (size_t)4 * Hdim * Hdim / 4);
    split_bf16_kernel<<<512, 256>>>(w1hh, wh + WOFF_G1HH, wl + WOFF_G1HH, (size_t)4 * Hdim * Hdim / 4);
    split_bf16_kernel<<<512, 256>>>(w2ih, wh + WOFF_G2IH, wl + WOFF_G2IH, (size_t)4 * Hdim * Hdim / 4);
    split_bf16_kernel<<<512, 256>>>(w2hh, wh + WOFF_G2HH, wl + WOFF_G2HH, (size_t)4 * Hdim * Hdim / 4);

    // split embedding (recurrence gather + GEMM both read the pairs)
    split_bf16_kernel<<<2048, 256>>>(emb, embh, embl, (size_t)Vsz * Hdim / 4);

    mog_lstm_kernel<<<NB, NT, R_SMEM_BYTES>>>(seq, m1b, b1ih, b1hh,
                                              m2b, b2ih, b2hh, hidp);

    gemm_bf16x3_bias<<<dim3((Bsz * Tlen) / 128, Vsz / 128), 256, G_SMEM_BYTES>>>(fc_b, outp);
}